// round 1
// baseline (speedup 1.0000x reference)
#include <cuda_runtime.h>
#include <cstdint>

#define NB 16
#define TT 128
#define VV 64
#define FF 16
#define TBL 8                   // timesteps per k1 block
#define NTB (TT / TBL)          // 16 t-blocks
#define TGROUPS 4               // t-groups per block (threads 256 = 64 i x 4 tg)
#define TPG (TBL / TGROUPS)     // 2 timesteps per group
#define PADF 20                 // padded feature stride (80B, 16B-aligned, low conflict)
#define NSLICE (NTB * TGROUPS)  // 64 partial slices

// partial[slice][n][j][i]  (64 * 16 * 64 * 64 floats = 16 MB)
__device__ __align__(16) float g_partial[NSLICE * NB * VV * VV];

// ---------------------------------------------------------------------------
// Kernel 1: partial score sums.
// score_partial[slice][n][j][i] = sum over 2 timesteps, 16 feats of
//                                 a[f] * |x[n,t,i,f] - x[n,t,j,f]|
// Packed f32x2 math: 2 elems per add2/fma2, abs via 64-bit AND (2x LOP3).
// ---------------------------------------------------------------------------
__global__ __launch_bounds__(256) void gl_partial_kernel(
    const float* __restrict__ x, const float* __restrict__ a)
{
    __shared__ __align__(16) float tile[TBL][VV][PADF];

    const int n  = blockIdx.y;
    const int tb = blockIdx.x;
    const int tid = threadIdx.x;
    const int i  = tid & 63;
    const int tg = tid >> 6;

    // Load tile: x[n, tb*8 : tb*8+8, :, :] is one contiguous 8192-float chunk.
    const float4* src = (const float4*)(x + (size_t)(n * TT + tb * TBL) * VV * FF);
    for (int q = tid; q < TBL * VV * 4; q += 256) {
        float4 v = src[q];
        int t  = q >> 8;          // 256 float4 per timestep
        int r  = q & 255;
        int vv = r >> 2;
        int f4 = r & 3;
        *(float4*)&tile[t][vv][f4 * 4] = v;
    }

    // Pack a[f] coefficient pairs into f32x2 (low 32 bits = even f).
    uint64_t af2[8];
#pragma unroll
    for (int k = 0; k < 8; k++) {
        af2[k] = (uint64_t)__float_as_uint(__ldg(&a[2 * k])) |
                 ((uint64_t)__float_as_uint(__ldg(&a[2 * k + 1])) << 32);
    }
    __syncthreads();

    // Register-cache this thread's i-row for its 2 timesteps, pre-negated
    // (sign-bit XOR) so the inner loop can use add2 instead of sub.
    uint64_t nzi[TPG][8];
#pragma unroll
    for (int tt = 0; tt < TPG; tt++) {
        const uint64_t* row = (const uint64_t*)&tile[tg * TPG + tt][i][0];
#pragma unroll
        for (int p = 0; p < 8; p++)
            nzi[tt][p] = row[p] ^ 0x8000000080000000ULL;
    }

    float* outp = &g_partial[(((size_t)(tb * TGROUPS + tg) * NB + n) * VV) * VV];

    for (int j = 0; j < VV; j++) {
        uint64_t acc[4] = {0ull, 0ull, 0ull, 0ull};   // packed (0.0f, 0.0f)
#pragma unroll
        for (int tt = 0; tt < TPG; tt++) {
            const uint64_t* zj = (const uint64_t*)&tile[tg * TPG + tt][j][0];
#pragma unroll
            for (int p = 0; p < 8; p++) {
                uint64_t d;
                // d = zj - zi  (zi pre-negated), packed pair
                asm("add.rn.f32x2 %0, %1, %2;"
                    : "=l"(d) : "l"(nzi[tt][p]), "l"(zj[p]));
                d &= 0x7FFFFFFF7FFFFFFFULL;           // packed |d|  (2x LOP3)
                asm("fma.rn.f32x2 %0, %1, %2, %3;"
                    : "=l"(acc[p & 3])
                    : "l"(af2[p]), "l"(d), "l"(acc[p & 3]));
            }
        }
        uint64_t s01, s23, s;
        asm("add.rn.f32x2 %0, %1, %2;" : "=l"(s01) : "l"(acc[0]), "l"(acc[1]));
        asm("add.rn.f32x2 %0, %1, %2;" : "=l"(s23) : "l"(acc[2]), "l"(acc[3]));
        asm("add.rn.f32x2 %0, %1, %2;" : "=l"(s)   : "l"(s01),   "l"(s23));
        float r = __uint_as_float((unsigned)s) +
                  __uint_as_float((unsigned)(s >> 32));
        outp[j * VV + i] = r;                          // lanes i-consecutive: coalesced
    }
}

// ---------------------------------------------------------------------------
// Kernel 2: reduce 64 slices, score = sum/T, e = exp(relu(score)),
// out[n,i,j] = e[i][j] / sum_i e[i][j]   (column-normalize over i).
// Grid: (4 j-quarters, 16 n), each block owns 16 j-columns.
// ---------------------------------------------------------------------------
__global__ __launch_bounds__(256) void gl_finalize_kernel(float* __restrict__ out)
{
    __shared__ float E[16][VV + 1];   // [local j][i], padded
    __shared__ float cinv[16];

    const int n     = blockIdx.y;
    const int jbase = blockIdx.x * 16;
    const int tid   = threadIdx.x;

    // Each thread reduces one float4 (4 consecutive i) across all 64 slices.
    {
        const float4* base =
            (const float4*)(g_partial + (size_t)n * VV * VV + (size_t)jbase * VV);
        const int slice_stride = NB * VV * VV / 4;    // in float4 units
        float4 s = make_float4(0.f, 0.f, 0.f, 0.f);
#pragma unroll 4
        for (int sl = 0; sl < NSLICE; sl++) {
            float4 v = base[(size_t)sl * slice_stride + tid];
            s.x += v.x; s.y += v.y; s.z += v.z; s.w += v.w;
        }
        const float inv = 1.0f / (float)TT;           // mean over time
        int lj = tid >> 4;
        int ii = (tid & 15) * 4;
        E[lj][ii + 0] = expf(fmaxf(s.x * inv, 0.f));
        E[lj][ii + 1] = expf(fmaxf(s.y * inv, 0.f));
        E[lj][ii + 2] = expf(fmaxf(s.z * inv, 0.f));
        E[lj][ii + 3] = expf(fmaxf(s.w * inv, 0.f));
    }
    __syncthreads();

    // Column sums (sum over i for each j): 16 rows of E, 2 per warp.
    const int w = tid >> 5, lane = tid & 31;
    for (int r = w; r < 16; r += 8) {
        float v = E[r][lane] + E[r][lane + 32];
#pragma unroll
        for (int o = 16; o; o >>= 1) v += __shfl_xor_sync(0xffffffffu, v, o);
        if (lane == 0) cinv[r] = 1.0f / v;
    }
    __syncthreads();

    for (int c = tid; c < 16 * VV; c += 256) {
        int ii = c >> 4;
        int lj = c & 15;
        out[(size_t)n * VV * VV + ii * VV + jbase + lj] = E[lj][ii] * cinv[lj];
    }
}

extern "C" void kernel_launch(void* const* d_in, const int* in_sizes, int n_in,
                              void* d_out, int out_size)
{
    const float* x = (const float*)d_in[0];       // [16,128,64,16] fp32
    const float* a = (const float*)d_in[1];       // [16,1] fp32
    float* out = (float*)d_out;                   // [16,64,64] fp32

    gl_partial_kernel<<<dim3(NTB, NB), 256>>>(x, a);
    gl_finalize_kernel<<<dim3(4, NB), 256>>>(out);
}

// round 2
// speedup vs baseline: 1.2440x; 1.2440x over previous
#include <cuda_runtime.h>
#include <cstdint>

#define NB 16
#define TT 128
#define VV 64
#define FF 16
#define TBL 4                   // timesteps per k1 block
#define NTB (TT / TBL)          // 32 t-blocks
#define JGROUPS 4               // j-groups per block (256 thr = 64 i x 4 jg)
#define JPG 16                  // j values per group
#define PADF 20                 // padded feature stride (80B, 16B-aligned)
#define NSLICE NTB              // 32 partial slices (each CTA fully sums its timesteps)

// partial[slice][n][j][i]  (32 * 16 * 64 * 64 floats = 8 MB)
__device__ __align__(16) float g_partial[NSLICE * NB * VV * VV];

// ---------------------------------------------------------------------------
// Kernel 1: partial score sums.
// partial[tb][n][j][i] = sum over TBL timesteps, 16 feats of
//                        a[f] * |x[n,t,i,f] - x[n,t,j,f]|
// Thread (i, jg): owns vertex-pair rows (i, j) for j in [jg*16, jg*16+16),
// accumulating ALL TBL timesteps in registers (acc[16] packed f32x2).
// Packed f32x2 math: add2 + 2xLOP3(abs) + fma2 per 2 elements.
// ---------------------------------------------------------------------------
__global__ __launch_bounds__(256, 2) void gl_partial_kernel(
    const float* __restrict__ x, const float* __restrict__ a)
{
    __shared__ __align__(16) float tile[TBL][VV][PADF];   // 20 KB

    const int n  = blockIdx.y;
    const int tb = blockIdx.x;
    const int tid = threadIdx.x;
    const int i     = tid & 63;
    const int jbase = (tid >> 6) * JPG;

    // Load tile: x[n, tb*TBL : +TBL, :, :] contiguous (TBL*64*16 floats).
    const float4* src = (const float4*)(x + (size_t)(n * TT + tb * TBL) * VV * FF);
#pragma unroll
    for (int q = tid; q < TBL * VV * 4; q += 256) {
        float4 v = src[q];
        int t  = q >> 8;          // 256 float4 per timestep
        int r  = q & 255;
        int vv = r >> 2;
        int f4 = r & 3;
        *(float4*)&tile[t][vv][f4 * 4] = v;
    }

    // Pack a[f] coefficient pairs into f32x2 (low 32 bits = even f).
    uint64_t af2[8];
#pragma unroll
    for (int k = 0; k < 8; k++) {
        af2[k] = (uint64_t)__float_as_uint(__ldg(&a[2 * k])) |
                 ((uint64_t)__float_as_uint(__ldg(&a[2 * k + 1])) << 32);
    }
    __syncthreads();

    uint64_t acc[JPG];
#pragma unroll
    for (int jj = 0; jj < JPG; jj++) acc[jj] = 0ull;

#pragma unroll
    for (int t = 0; t < TBL; t++) {
        // Register-cache this thread's i-row, pre-negated (sign XOR) so the
        // inner loop uses add2 instead of sub.
        const ulonglong2* zr = (const ulonglong2*)&tile[t][i][0];
        ulonglong2 zi0 = zr[0], zi1 = zr[1], zi2 = zr[2], zi3 = zr[3];
        uint64_t nzi[8];
        nzi[0] = zi0.x ^ 0x8000000080000000ULL;
        nzi[1] = zi0.y ^ 0x8000000080000000ULL;
        nzi[2] = zi1.x ^ 0x8000000080000000ULL;
        nzi[3] = zi1.y ^ 0x8000000080000000ULL;
        nzi[4] = zi2.x ^ 0x8000000080000000ULL;
        nzi[5] = zi2.y ^ 0x8000000080000000ULL;
        nzi[6] = zi3.x ^ 0x8000000080000000ULL;
        nzi[7] = zi3.y ^ 0x8000000080000000ULL;

#pragma unroll
        for (int jj = 0; jj < JPG; jj++) {
            // j-row is warp-uniform -> LDS broadcast (cheap).
            const ulonglong2* zjr = (const ulonglong2*)&tile[t][jbase + jj][0];
            ulonglong2 q0 = zjr[0], q1 = zjr[1], q2 = zjr[2], q3 = zjr[3];
            uint64_t zj[8] = {q0.x, q0.y, q1.x, q1.y, q2.x, q2.y, q3.x, q3.y};
#pragma unroll
            for (int p = 0; p < 8; p++) {
                uint64_t d;
                asm("add.rn.f32x2 %0, %1, %2;"
                    : "=l"(d) : "l"(nzi[p]), "l"(zj[p]));
                d &= 0x7FFFFFFF7FFFFFFFULL;           // packed |d| (2x LOP3)
                asm("fma.rn.f32x2 %0, %1, %2, %3;"
                    : "=l"(acc[jj]) : "l"(af2[p]), "l"(d), "l"(acc[jj]));
            }
        }
    }

    // Store: partial[tb][n][j][i], lanes i-consecutive -> coalesced.
    float* outp = &g_partial[(((size_t)tb * NB + n) * VV + jbase) * VV + i];
#pragma unroll
    for (int jj = 0; jj < JPG; jj++) {
        float r = __uint_as_float((unsigned)acc[jj]) +
                  __uint_as_float((unsigned)(acc[jj] >> 32));
        outp[jj * VV] = r;
    }
}

// ---------------------------------------------------------------------------
// Kernel 2: reduce 32 slices, score = sum/T, e = exp(relu(score)),
// out[n,i,j] = e[i][j] / sum_i e[i][j]   (normalize over i, per column j).
// Grid: (8 j-octants, 16 n). One warp owns one j-column (64 i values).
// ---------------------------------------------------------------------------
__global__ __launch_bounds__(256) void gl_finalize_kernel(float* __restrict__ out)
{
    __shared__ float E[8][VV];        // [local j][i]

    const int n     = blockIdx.y;
    const int jbase = blockIdx.x * 8;
    const int tid   = threadIdx.x;
    const int lj    = tid >> 5;       // local j (warp index)
    const int lane  = tid & 31;
    const int j     = jbase + lj;

    const float* base = g_partial + (((size_t)n * VV + j) * VV);
    const size_t slice_stride = (size_t)NB * VV * VV;

    float s0 = 0.f, s1 = 0.f;
#pragma unroll
    for (int sl = 0; sl < NSLICE; sl++) {
        const float* p = base + (size_t)sl * slice_stride;
        s0 += p[lane];
        s1 += p[lane + 32];
    }

    const float inv = 1.0f / (float)TT;               // mean over time
    float e0 = expf(fmaxf(s0 * inv, 0.f));
    float e1 = expf(fmaxf(s1 * inv, 0.f));

    // Column sum over all 64 i (both halves), full-warp butterfly.
    float v = e0 + e1;
#pragma unroll
    for (int o = 16; o; o >>= 1) v += __shfl_xor_sync(0xffffffffu, v, o);
    float cinv = __frcp_rn(v);                        // same in all lanes

    E[lj][lane]      = e0 * cinv;
    E[lj][lane + 32] = e1 * cinv;
    __syncthreads();

    // Coalesced-ish transpose store: out[n][i][jbase + jq].
#pragma unroll
    for (int c = tid; c < 8 * VV; c += 256) {
        int ii = c >> 3;
        int jq = c & 7;
        out[(size_t)n * VV * VV + ii * VV + jbase + jq] = E[jq][ii];
    }
}

extern "C" void kernel_launch(void* const* d_in, const int* in_sizes, int n_in,
                              void* d_out, int out_size)
{
    const float* x = (const float*)d_in[0];       // [16,128,64,16] fp32
    const float* a = (const float*)d_in[1];       // [16,1] fp32
    float* out = (float*)d_out;                   // [16,64,64] fp32

    gl_partial_kernel<<<dim3(NTB, NB), 256>>>(x, a);
    gl_finalize_kernel<<<dim3(8, NB), 256>>>(out);
}

// round 3
// speedup vs baseline: 1.3033x; 1.0477x over previous
#include <cuda_runtime.h>
#include <cstdint>

#define NB 16
#define TT 128
#define VV 64
#define FF 16
#define TBL 8                   // timesteps per k1 block
#define NTB (TT / TBL)          // 16 t-blocks
#define JPG 16                  // j values per thread-group
#define PADF 20                 // padded feature stride (80B, 16B-aligned)
#define NSLICE NTB              // 16 partial slices

// partial[slice][n][j][i]  (16 * 16 * 64 * 64 floats = 4 MB)
__device__ __align__(16) float g_partial[NSLICE * NB * VV * VV];

// ---------------------------------------------------------------------------
// Kernel 1: partial score sums.
// partial[tb][n][j][i] = sum over TBL=8 timesteps, 16 feats of
//                        a[f] * |x[n,t,i,f] - x[n,t,j,f]|
// 256 thr = 64 i-lanes x 4 j-groups; each thread owns (i, 16 j) and
// accumulates all 8 timesteps in 16 packed-f32x2 registers.
// t-loop rolled (I$: body ~9KB fits L1.5), jj fully unrolled (static acc idx).
// ---------------------------------------------------------------------------
__global__ __launch_bounds__(256, 2) void gl_partial_kernel(
    const float* __restrict__ x, const float* __restrict__ a)
{
    __shared__ __align__(16) float tile[TBL][VV][PADF];   // 40 KB

    const int n  = blockIdx.y;
    const int tb = blockIdx.x;
    const int tid = threadIdx.x;
    const int i     = tid & 63;
    const int jbase = (tid >> 6) * JPG;

    // Load tile: x[n, tb*8 : +8, :, :] contiguous (8192 floats).
    const float4* src = (const float4*)(x + (size_t)(n * TT + tb * TBL) * VV * FF);
#pragma unroll
    for (int q = tid; q < TBL * VV * 4; q += 256) {
        float4 v = src[q];
        int t  = q >> 8;          // 256 float4 per timestep
        int r  = q & 255;
        int vv = r >> 2;
        int f4 = r & 3;
        *(float4*)&tile[t][vv][f4 * 4] = v;
    }

    // Pack a[f] coefficient pairs into f32x2 (low 32 bits = even f).
    uint64_t af2[8];
#pragma unroll
    for (int k = 0; k < 8; k++) {
        af2[k] = (uint64_t)__float_as_uint(__ldg(&a[2 * k])) |
                 ((uint64_t)__float_as_uint(__ldg(&a[2 * k + 1])) << 32);
    }
    __syncthreads();

    uint64_t acc[JPG];
#pragma unroll
    for (int jj = 0; jj < JPG; jj++) acc[jj] = 0ull;

#pragma unroll 1
    for (int t = 0; t < TBL; t++) {
        // Register-cache this thread's i-row, pre-negated (sign XOR) so the
        // inner loop uses add2 instead of sub.
        const ulonglong2* zr = (const ulonglong2*)&tile[t][i][0];
        ulonglong2 zi0 = zr[0], zi1 = zr[1], zi2 = zr[2], zi3 = zr[3];
        uint64_t nzi[8];
        nzi[0] = zi0.x ^ 0x8000000080000000ULL;
        nzi[1] = zi0.y ^ 0x8000000080000000ULL;
        nzi[2] = zi1.x ^ 0x8000000080000000ULL;
        nzi[3] = zi1.y ^ 0x8000000080000000ULL;
        nzi[4] = zi2.x ^ 0x8000000080000000ULL;
        nzi[5] = zi2.y ^ 0x8000000080000000ULL;
        nzi[6] = zi3.x ^ 0x8000000080000000ULL;
        nzi[7] = zi3.y ^ 0x8000000080000000ULL;

#pragma unroll
        for (int jj = 0; jj < JPG; jj++) {
            // j-row is warp-uniform -> LDS.128 broadcast (conflict-free).
            const ulonglong2* zjr = (const ulonglong2*)&tile[t][jbase + jj][0];
            ulonglong2 q0 = zjr[0], q1 = zjr[1], q2 = zjr[2], q3 = zjr[3];
            uint64_t zj[8] = {q0.x, q0.y, q1.x, q1.y, q2.x, q2.y, q3.x, q3.y};
#pragma unroll
            for (int p = 0; p < 8; p++) {
                uint64_t d;
                asm("add.rn.f32x2 %0, %1, %2;"
                    : "=l"(d) : "l"(nzi[p]), "l"(zj[p]));
                d &= 0x7FFFFFFF7FFFFFFFULL;           // packed |d| (2x LOP3)
                asm("fma.rn.f32x2 %0, %1, %2, %3;"
                    : "=l"(acc[jj]) : "l"(af2[p]), "l"(d), "l"(acc[jj]));
            }
        }
    }

    // Store: partial[tb][n][j][i], lanes i-consecutive -> coalesced.
    float* outp = &g_partial[(((size_t)tb * NB + n) * VV + jbase) * VV + i];
#pragma unroll
    for (int jj = 0; jj < JPG; jj++) {
        float r = __uint_as_float((unsigned)acc[jj]) +
                  __uint_as_float((unsigned)(acc[jj] >> 32));
        outp[jj * VV] = r;
    }
}

// ---------------------------------------------------------------------------
// Kernel 2: reduce 16 slices, score = sum/T, e = exp(relu(score)),
// out[n,i,j] = e[i][j] / sum_i e[i][j]   (normalize over i, per column j).
// Grid (8 j-octants, 16 n); warp w owns j-column jbase+w; lane holds i-pair
// (2i, 2i+1) via float2; 16 fully independent slice loads per thread (MLP 16).
// ---------------------------------------------------------------------------
__global__ __launch_bounds__(256) void gl_finalize_kernel(float* __restrict__ out)
{
    __shared__ float E[8][VV + 2];    // [local j][i], padded

    const int n     = blockIdx.y;
    const int jbase = blockIdx.x * 8;
    const int tid   = threadIdx.x;
    const int lj    = tid >> 5;       // local j (warp index)
    const int lane  = tid & 31;
    const int j     = jbase + lj;

    const float2* base =
        (const float2*)(g_partial + (((size_t)n * VV + j) * VV)) + lane;
    const size_t sstride = (size_t)NB * VV * VV / 2;  // float2 units

    float sx = 0.f, sy = 0.f;
#pragma unroll
    for (int sl = 0; sl < NSLICE; sl++) {
        float2 v = base[(size_t)sl * sstride];
        sx += v.x; sy += v.y;
    }

    const float inv = 1.0f / (float)TT;               // mean over time
    float e0 = expf(fmaxf(sx * inv, 0.f));
    float e1 = expf(fmaxf(sy * inv, 0.f));

    // Column sum over all 64 i, full-warp butterfly.
    float v = e0 + e1;
#pragma unroll
    for (int o = 16; o; o >>= 1) v += __shfl_xor_sync(0xffffffffu, v, o);
    float cinv = 1.0f / v;

    E[lj][lane * 2]     = e0 * cinv;
    E[lj][lane * 2 + 1] = e1 * cinv;
    __syncthreads();

    // Transposed store: out[n][ii][jbase + 2q .. +2q+1] as float2.
    {
        int ii = tid >> 2;            // 0..63
        int q  = tid & 3;             // j-pair index
        float2 w;
        w.x = E[2 * q][ii];
        w.y = E[2 * q + 1][ii];
        *(float2*)&out[(size_t)n * VV * VV + ii * VV + jbase + 2 * q] = w;
    }
}

extern "C" void kernel_launch(void* const* d_in, const int* in_sizes, int n_in,
                              void* d_out, int out_size)
{
    const float* x = (const float*)d_in[0];       // [16,128,64,16] fp32
    const float* a = (const float*)d_in[1];       // [16,1] fp32
    float* out = (float*)d_out;                   // [16,64,64] fp32

    gl_partial_kernel<<<dim3(NTB, NB), 256>>>(x, a);
    gl_finalize_kernel<<<dim3(8, NB), 256>>>(out);
}